// round 13
// baseline (speedup 1.0000x reference)
#include <cuda_runtime.h>
#include <cuda_bf16.h>
#include <cstdint>

// BarrierNet: layer1 (5->128) on FMA pipe (exact fp32, per-lane rows, uniform
// w1 broadcast LDS) -> split hi/lo bf16 -> per-warp SMEM strip -> ldmatrix A
// fragments. Layer2 (128->64) 3-term split bf16 m16n8k16 on tensor pipe,
// term-round interleaved. Warp tile 32 rows x 64 outputs, 2 CTAs/SM,
// persistent 296 blocks over 256-row tiles.

__device__ __forceinline__ uint32_t smem_u32(const void* p) {
    uint32_t a;
    asm("{ .reg .u64 t; cvta.to.shared.u64 t, %1; cvt.u32.u64 %0, t; }" : "=r"(a) : "l"(p));
    return a;
}
__device__ __forceinline__ void ldmx4(uint32_t& r0, uint32_t& r1, uint32_t& r2, uint32_t& r3, uint32_t a) {
    asm volatile("ldmatrix.sync.aligned.m8n8.x4.shared.b16 {%0,%1,%2,%3}, [%4];"
                 : "=r"(r0), "=r"(r1), "=r"(r2), "=r"(r3) : "r"(a));
}
__device__ __forceinline__ void mma16(float* c, const uint32_t* a, const uint32_t* b) {
    asm volatile("mma.sync.aligned.m16n8k16.row.col.f32.bf16.bf16.f32 "
                 "{%0,%1,%2,%3}, {%4,%5,%6,%7}, {%8,%9}, {%0,%1,%2,%3};"
                 : "+f"(c[0]), "+f"(c[1]), "+f"(c[2]), "+f"(c[3])
                 : "r"(a[0]), "r"(a[1]), "r"(a[2]), "r"(a[3]), "r"(b[0]), "r"(b[1]));
}
// pack two f32 -> bf16x2: first asm operand -> HIGH half
__device__ __forceinline__ uint32_t cvt2(float hi, float lo) {
    uint32_t r;
    asm("cvt.rn.bf16x2.f32 %0, %1, %2;" : "=r"(r) : "f"(hi), "f"(lo));
    return r;
}
__device__ __forceinline__ float lo_f(uint32_t p) { return __uint_as_float(p << 16); }
__device__ __forceinline__ float hi_f(uint32_t p) { return __uint_as_float(p & 0xFFFF0000u); }

static constexpr int TILE_M = 256;

struct Smem {
    float  x[256][8];        // 8KB  (x0..x4, 0,0,0)
    float  w1f[128][8];      // 4KB  (w1[k][0..4], b1[k], 0, 0)
    uint4  w2h[64][16];      // 16KB swizzled bf16-hi
    uint4  w2l[64][16];      // 16KB swizzled bf16-lo
    uint4  hh[8][2][64];     // 16KB per-warp double-buffered h-hi (32 rows x 32B)
    uint4  hl[8][2][64];     // 16KB h-lo
    float4 ep[64];           // 1KB  (b2, w3row0, w3row1, 0)
    float  b3[4], ms[8];
};

extern __shared__ char smem_raw[];

__global__ __launch_bounds__(256, 2) void barriernet_mma_kernel(
    const float* __restrict__ x,
    const float* __restrict__ mean_, const float* __restrict__ std_,
    const float* __restrict__ w1,  const float* __restrict__ b1,
    const float* __restrict__ w21, const float* __restrict__ b21,
    const float* __restrict__ w22, const float* __restrict__ b22,
    const float* __restrict__ w31, const float* __restrict__ b31,
    const float* __restrict__ w32, const float* __restrict__ b32,
    float2* __restrict__ out, int B, int numTiles)
{
    Smem* S = (Smem*)smem_raw;
    const int t = threadIdx.x;

    // ---- stage weights ONCE per block ----
    if (t < 128) {
#pragma unroll
        for (int i = 0; i < 5; i++) S->w1f[t][i] = w1[t * 5 + i];
        S->w1f[t][5] = b1[t]; S->w1f[t][6] = 0.f; S->w1f[t][7] = 0.f;
    }
    for (int i = t; i < 64 * 16; i += 256) {
        const int n = i >> 4, c = i & 15;
        const float* src = (n < 32) ? (w21 + n * 128 + c * 8)
                                    : (w22 + (n - 32) * 128 + c * 8);
        uint4 h, l;
        h.x = cvt2(src[1], src[0]); l.x = cvt2(src[1] - hi_f(h.x), src[0] - lo_f(h.x));
        h.y = cvt2(src[3], src[2]); l.y = cvt2(src[3] - hi_f(h.y), src[2] - lo_f(h.y));
        h.z = cvt2(src[5], src[4]); l.z = cvt2(src[5] - hi_f(h.z), src[4] - lo_f(h.z));
        h.w = cvt2(src[7], src[6]); l.w = cvt2(src[7] - hi_f(h.w), src[6] - lo_f(h.w));
        const int cs = c ^ (n & 7);
        S->w2h[n][cs] = h; S->w2l[n][cs] = l;
    }
    if (t < 64) {
        S->ep[t] = (t < 32) ? make_float4(b21[t], w31[t], w31[32 + t], 0.f)
                            : make_float4(b22[t - 32], w32[t - 32], w32[t], 0.f);
    }
    if (t < 4) S->b3[t] = (t < 2) ? b31[t] : b32[t - 2];
    if (t >= 8 && t < 16) S->ms[t - 8] = (t < 12) ? mean_[t - 8] : std_[t - 12];

    const int wid = t >> 5, lane = t & 31;
    const int g = lane >> 2, tig = lane & 3;
    const int rb = wid * 32;
    const uint32_t w2h_base = smem_u32(S->w2h), w2l_base = smem_u32(S->w2l);
    const uint32_t hh_base = smem_u32(&S->hh[wid][0][0]);
    const uint32_t hl_base = smem_u32(&S->hl[wid][0][0]);
    const uint32_t aoff = (uint32_t)((lane & 15) * 32 + ((lane >> 4) << 4));
    const uint32_t nrow  = (uint32_t)((lane & 7) + ((lane & 16) >> 1));
    const uint32_t klane = (uint32_t)((lane >> 3) & 1);
    const int rl = rb + (tig >> 1) * 16 + (tig & 1) * 8 + g;

    for (int tile = blockIdx.x; tile < numTiles; tile += gridDim.x) {
        const int tbase = tile * TILE_M;
        __syncthreads();   // previous tile fully consumed s_x (and first-pass staging)
        // ---- stage x ----
        for (int i = t; i < 256 * 8; i += 256) {
            const int r = i >> 3, k = i & 7;
            float v = 0.f;
            if (k < 5) { const int gr = min(tbase + r, B - 1); v = x[(size_t)gr * 5 + k]; }
            S->x[r][k] = v;
        }
        __syncthreads();

        // this lane's row for layer-1 compute
        const int myrow = rb + lane;
        const float4 xv = *(const float4*)&S->x[myrow][0];
        const float  x4v = S->x[myrow][4];

        float acc[2][8][4];
#pragma unroll
        for (int s = 0; s < 2; s++)
#pragma unroll
            for (int nf = 0; nf < 8; nf++)
#pragma unroll
                for (int q = 0; q < 4; q++) acc[s][nf][q] = 0.f;

#pragma unroll
        for (int j = 0; j < 8; j++) {
            const uint32_t bufoff = (uint32_t)((j & 1) * 1024);
            // ---- layer 1 on FMA pipe: 16 h for my row, exact fp32 ----
#pragma unroll
            for (int gh = 0; gh < 2; gh++) {
                float h[8];
#pragma unroll
                for (int kk = 0; kk < 8; kk++) {
                    const int k = j * 16 + gh * 8 + kk;
                    const float4 wa = *(const float4*)&S->w1f[k][0];
                    const float2 wb = *(const float2*)&S->w1f[k][4];
                    float hv = fmaf(xv.x, wa.x, fmaf(xv.y, wa.y, fmaf(xv.z, wa.z,
                               fmaf(xv.w, wa.w, fmaf(x4v, wb.x, wb.y)))));
                    h[kk] = fmaxf(hv, 0.f);
                }
                uint32_t ph[4], pl[4];
#pragma unroll
                for (int p = 0; p < 4; p++) {
                    ph[p] = cvt2(h[2 * p + 1], h[2 * p]);
                    pl[p] = cvt2(h[2 * p + 1] - hi_f(ph[p]), h[2 * p] - lo_f(ph[p]));
                }
                S->hh[wid][j & 1][lane * 2 + gh] = make_uint4(ph[0], ph[1], ph[2], ph[3]);
                S->hl[wid][j & 1][lane * 2 + gh] = make_uint4(pl[0], pl[1], pl[2], pl[3]);
            }
            __syncwarp();

            // ---- A fragments via ldmatrix (standard layout) ----
            uint32_t Ah[2][4], Al[2][4];
#pragma unroll
            for (int s = 0; s < 2; s++) {
                const uint32_t a = bufoff + (uint32_t)(s * 512) + aoff;
                ldmx4(Ah[s][0], Ah[s][1], Ah[s][2], Ah[s][3], hh_base + a);
                ldmx4(Al[s][0], Al[s][1], Al[s][2], Al[s][3], hl_base + a);
            }

            // ---- layer 2: two halves; loads hoisted, term-rounds interleaved ----
#pragma unroll
            for (int half = 0; half < 2; half++) {
                uint32_t bh[2][2][2], bl[2][2][2];   // [pp][frag][reg]
#pragma unroll
                for (int pp = 0; pp < 2; pp++) {
                    const uint32_t n = nrow + (uint32_t)((half * 2 + pp) * 16);
                    const uint32_t a = (n << 8) + ((((uint32_t)(2 * j) + klane) ^ (n & 7)) << 4);
                    ldmx4(bh[pp][0][0], bh[pp][0][1], bh[pp][1][0], bh[pp][1][1], w2h_base + a);
                    ldmx4(bl[pp][0][0], bl[pp][0][1], bl[pp][1][0], bl[pp][1][1], w2l_base + a);
                }
#pragma unroll
                for (int term = 0; term < 3; term++) {
#pragma unroll
                    for (int pp = 0; pp < 2; pp++)
#pragma unroll
                        for (int f = 0; f < 2; f++)
#pragma unroll
                            for (int s = 0; s < 2; s++) {
                                const int ai = (half * 2 + pp) * 2 + f;
                                const uint32_t* A = (term == 1) ? Al[s] : Ah[s];
                                const uint32_t* Bf = (term == 2) ? bl[pp][f] : bh[pp][f];
                                mma16(acc[s][ai], A, Bf);
                            }
                }
            }
        }

        // ---- epilogue: bias+relu, layer-3 dots, quad reduction, QP ----
        float P[4][4];
#pragma unroll
        for (int s = 0; s < 2; s++)
#pragma unroll
            for (int o = 0; o < 2; o++) {
                float pax = 0.f, pay = 0.f, pbx = 0.f, pby = 0.f;
#pragma unroll
                for (int nf = 0; nf < 8; nf++) {
                    const int n0 = nf * 8 + tig * 2;
                    const float4 e0 = S->ep[n0];
                    const float4 e1 = S->ep[n0 + 1];
                    const float y0 = fmaxf(acc[s][nf][o * 2 + 0] + e0.x, 0.f);
                    const float y1 = fmaxf(acc[s][nf][o * 2 + 1] + e1.x, 0.f);
                    if (nf < 4) {
                        pax = fmaf(y0, e0.y, fmaf(y1, e1.y, pax));
                        pay = fmaf(y0, e0.z, fmaf(y1, e1.z, pay));
                    } else {
                        pbx = fmaf(y0, e0.y, fmaf(y1, e1.y, pbx));
                        pby = fmaf(y0, e0.z, fmaf(y1, e1.z, pby));
                    }
                }
                P[s * 2 + o][0] = pax; P[s * 2 + o][1] = pay;
                P[s * 2 + o][2] = pbx; P[s * 2 + o][3] = pby;
            }
#pragma unroll
        for (int sl = 0; sl < 4; sl++)
#pragma unroll
            for (int c = 0; c < 4; c++) {
                P[sl][c] += __shfl_xor_sync(0xFFFFFFFFu, P[sl][c], 1);
                P[sl][c] += __shfl_xor_sync(0xFFFFFFFFu, P[sl][c], 2);
            }

        float uax, uay, ubx, uby;
        if      (tig == 0) { uax = P[0][0]; uay = P[0][1]; ubx = P[0][2]; uby = P[0][3]; }
        else if (tig == 1) { uax = P[1][0]; uay = P[1][1]; ubx = P[1][2]; uby = P[1][3]; }
        else if (tig == 2) { uax = P[2][0]; uay = P[2][1]; ubx = P[2][2]; uby = P[2][3]; }
        else               { uax = P[3][0]; uay = P[3][1]; ubx = P[3][2]; uby = P[3][3]; }

        const int gr = tbase + rl;
        if (gr < B) {
            const float px = S->x[rl][0] * S->ms[4] + S->ms[0];
            const float py = S->x[rl][1] * S->ms[5] + S->ms[1];
            const float th = S->x[rl][2] * S->ms[6] + S->ms[2];
            const float v  = S->x[rl][3] * S->ms[7] + S->ms[3];
            float s, c;
            sincosf(th, &s, &c);
            const float dx = px - 40.0f, dy = py - 15.0f;
            const float barrier = dx * dx + dy * dy - 36.0f;
            const float bdot = 2.0f * dx * v * c + 2.0f * dy * v * s;
            const float Lf2b = 2.0f * v * v;
            const float g1 = -(-2.0f * dx * v * s + 2.0f * dy * v * c);
            const float g2 = -(2.0f * dx * c + 2.0f * dy * s);

            const float u0x = -(uax + S->b3[0]);
            const float u0y = -(uay + S->b3[1]);
            const float z1 = ubx + S->b3[2];
            const float z2 = uby + S->b3[3];
            const float x32_0 = 4.0f / (1.0f + expf(-z1));
            const float x32_1 = 4.0f / (1.0f + expf(-z2));

            const float hq   = Lf2b + (x32_0 + x32_1) * bdot + x32_0 * x32_1 * barrier;
            const float viol = g1 * u0x + g2 * u0y - hq;
            const float gg   = g1 * g1 + g2 * g2;
            const float lam  = fmaxf(viol, 0.f) / (gg + 1e-12f);

            out[gr] = make_float2(u0x - lam * g1, u0y - lam * g2);
        }
    }
}

extern "C" void kernel_launch(void* const* d_in, const int* in_sizes, int n_in,
                              void* d_out, int out_size) {
    const float* x     = (const float*)d_in[0];
    const float* mean_ = (const float*)d_in[2];
    const float* std_  = (const float*)d_in[3];
    const float* w1    = (const float*)d_in[4];
    const float* b1    = (const float*)d_in[5];
    const float* w21   = (const float*)d_in[6];
    const float* b21   = (const float*)d_in[7];
    const float* w22   = (const float*)d_in[8];
    const float* b22   = (const float*)d_in[9];
    const float* w31   = (const float*)d_in[10];
    const float* b31   = (const float*)d_in[11];
    const float* w32   = (const float*)d_in[12];
    const float* b32   = (const float*)d_in[13];

    const int B = in_sizes[0] / 5;
    const int numTiles = (B + TILE_M - 1) / TILE_M;
    const int smemBytes = (int)sizeof(Smem);

    cudaFuncSetAttribute(barriernet_mma_kernel,
                         cudaFuncAttributeMaxDynamicSharedMemorySize, smemBytes);

    const int blocks = 296;   // 2 CTAs/SM x 148 SMs, persistent over tiles
    barriernet_mma_kernel<<<blocks, 256, smemBytes>>>(
        x, mean_, std_, w1, b1, w21, b21, w22, b22, w31, b31, w32, b32,
        (float2*)d_out, B, numTiles);
}

// round 17
// speedup vs baseline: 1.5002x; 1.5002x over previous
#include <cuda_runtime.h>
#include <cuda_fp16.h>
#include <cstdint>

// BarrierNet via mma.sync (HMMA) fp16 split-precision, sm_80-compatible PTX.
// Layer1 (5->128): m16n8k16 ([xh|xl]x[wh|wh]) + m16n8k8 (xh x w1lo) => ~exact.
// D fragments relu'd/split hi-lo fp16/repacked in registers as layer2 A frags.
// Layer2 (128->64): 2-term fp16 (Ah*Bh + Al*Bh), B = fp16(W2) single copy.
// Warp tile 32 rows x 64 outputs, 2 CTAs/SM, persistent 296 blocks.

__device__ __forceinline__ uint32_t smem_u32(const void* p) {
    uint32_t a;
    asm("{ .reg .u64 t; cvta.to.shared.u64 t, %1; cvt.u32.u64 %0, t; }" : "=r"(a) : "l"(p));
    return a;
}
__device__ __forceinline__ void ldmx4(uint32_t& r0, uint32_t& r1, uint32_t& r2, uint32_t& r3, uint32_t a) {
    asm volatile("ldmatrix.sync.aligned.m8n8.x4.shared.b16 {%0,%1,%2,%3}, [%4];"
                 : "=r"(r0), "=r"(r1), "=r"(r2), "=r"(r3) : "r"(a));
}
__device__ __forceinline__ void ldmx2(uint32_t& r0, uint32_t& r1, uint32_t a) {
    asm volatile("ldmatrix.sync.aligned.m8n8.x2.shared.b16 {%0,%1}, [%2];"
                 : "=r"(r0), "=r"(r1) : "r"(a));
}
__device__ __forceinline__ void mma16(float* c, const uint32_t* a, const uint32_t* b) {
    asm volatile("mma.sync.aligned.m16n8k16.row.col.f32.f16.f16.f32 "
                 "{%0,%1,%2,%3}, {%4,%5,%6,%7}, {%8,%9}, {%0,%1,%2,%3};"
                 : "+f"(c[0]), "+f"(c[1]), "+f"(c[2]), "+f"(c[3])
                 : "r"(a[0]), "r"(a[1]), "r"(a[2]), "r"(a[3]), "r"(b[0]), "r"(b[1]));
}
__device__ __forceinline__ void mma8(float* c, const uint32_t* a, uint32_t b) {
    asm volatile("mma.sync.aligned.m16n8k8.row.col.f32.f16.f16.f32 "
                 "{%0,%1,%2,%3}, {%4,%5}, {%6}, {%0,%1,%2,%3};"
                 : "+f"(c[0]), "+f"(c[1]), "+f"(c[2]), "+f"(c[3])
                 : "r"(a[0]), "r"(a[1]), "r"(b));
}
// pack two f32 -> f16x2: FIRST asm source operand -> HIGH half
__device__ __forceinline__ uint32_t cvt2(float hi, float lo) {
    uint32_t r;
    asm("cvt.rn.f16x2.f32 %0, %1, %2;" : "=r"(r) : "f"(hi), "f"(lo));
    return r;
}
__device__ __forceinline__ float lo_f(uint32_t p) {
    __half2 h = *reinterpret_cast<__half2*>(&p);
    return __low2float(h);
}
__device__ __forceinline__ float hi_f(uint32_t p) {
    __half2 h = *reinterpret_cast<__half2*>(&p);
    return __high2float(h);
}

static constexpr int TILE_M = 256;

__global__ __launch_bounds__(256, 2) void barriernet_mma_kernel(
    const float* __restrict__ x,
    const float* __restrict__ mean_, const float* __restrict__ std_,
    const float* __restrict__ w1,  const float* __restrict__ b1,
    const float* __restrict__ w21, const float* __restrict__ b21,
    const float* __restrict__ w22, const float* __restrict__ b22,
    const float* __restrict__ w31, const float* __restrict__ b31,
    const float* __restrict__ w32, const float* __restrict__ b32,
    float2* __restrict__ out, int B, int numTiles)
{
    __shared__ __align__(16) float s_x[256][8];       // 8KB: x0..x4, 1, 0, 0
    __shared__ __align__(16) uint4 s_w1h[128], s_w1l[128];   // [n][k8] f16x2x4
    __shared__ __align__(16) uint4 s_w2h[64][16];     // [n][chunk] swizzled fp16 W2
    __shared__ __align__(16) float4 s_ep[64];         // (b2, w3row0, w3row1, 0)
    __shared__ float s_b3[4], s_ms[8];

    const int t = threadIdx.x;

    // ---- stage weights ONCE per block ----
    if (t < 128) {
        float v[8];
#pragma unroll
        for (int i = 0; i < 5; i++) v[i] = w1[t * 5 + i];
        v[5] = b1[t]; v[6] = 0.f; v[7] = 0.f;
        uint4 h, l;
        h.x = cvt2(v[1], v[0]); l.x = cvt2(v[1] - hi_f(h.x), v[0] - lo_f(h.x));
        h.y = cvt2(v[3], v[2]); l.y = cvt2(v[3] - hi_f(h.y), v[2] - lo_f(h.y));
        h.z = cvt2(v[5], v[4]); l.z = cvt2(v[5] - hi_f(h.z), v[4] - lo_f(h.z));
        h.w = 0u;               l.w = 0u;
        s_w1h[t] = h; s_w1l[t] = l;
    }
    for (int i = t; i < 64 * 16; i += 256) {
        const int n = i >> 4, c = i & 15;
        const float* src = (n < 32) ? (w21 + n * 128 + c * 8)
                                    : (w22 + (n - 32) * 128 + c * 8);
        uint4 h;
        h.x = cvt2(src[1], src[0]);
        h.y = cvt2(src[3], src[2]);
        h.z = cvt2(src[5], src[4]);
        h.w = cvt2(src[7], src[6]);
        const int cs = c ^ (n & 7);
        s_w2h[n][cs] = h;
    }
    if (t < 64) {
        s_ep[t] = (t < 32) ? make_float4(b21[t], w31[t], w31[32 + t], 0.f)
                           : make_float4(b22[t - 32], w32[t - 32], w32[t], 0.f);
    }
    if (t < 4) s_b3[t] = (t < 2) ? b31[t] : b32[t - 2];
    if (t >= 8 && t < 16) s_ms[t - 8] = (t < 12) ? mean_[t - 8] : std_[t - 12];

    const int wid = t >> 5, lane = t & 31;
    const int g = lane >> 2, tig = lane & 3;
    const int rb = wid * 32;
    const uint32_t w1h_base = smem_u32(s_w1h), w1l_base = smem_u32(s_w1l);
    const uint32_t w2h_base = smem_u32(s_w2h);
    const uint32_t nrow  = (uint32_t)((lane & 7) + ((lane & 16) >> 1));
    const uint32_t klane = (uint32_t)((lane >> 3) & 1);
    const int rl = rb + (tig >> 1) * 16 + (tig & 1) * 8 + g;

    for (int tile = blockIdx.x; tile < numTiles; tile += gridDim.x) {
        const int tbase = tile * TILE_M;
        __syncthreads();   // previous tile fully consumed s_x
        // ---- stage x (padded, bias column at k=5) ----
        for (int i = t; i < 256 * 8; i += 256) {
            const int r = i >> 3, k = i & 7;
            float v;
            if (k < 5) { const int gr = min(tbase + r, B - 1); v = x[(size_t)gr * 5 + k]; }
            else v = (k == 5) ? 1.0f : 0.0f;
            s_x[r][k] = v;
        }
        __syncthreads();

        // ---- x fragments (rows g/g+8 per s-slice, k=tig*2,+1) ----
        uint32_t xh[2][2], xl[2][2];
#pragma unroll
        for (int s = 0; s < 2; s++) {
            const float2 v0 = *(const float2*)&s_x[rb + s * 16 + g][tig * 2];
            const float2 v1 = *(const float2*)&s_x[rb + s * 16 + g + 8][tig * 2];
            xh[s][0] = cvt2(v0.y, v0.x);
            xl[s][0] = cvt2(v0.y - hi_f(xh[s][0]), v0.x - lo_f(xh[s][0]));
            xh[s][1] = cvt2(v1.y, v1.x);
            xl[s][1] = cvt2(v1.y - hi_f(xh[s][1]), v1.x - lo_f(xh[s][1]));
        }

        float acc[2][8][4];
#pragma unroll
        for (int s = 0; s < 2; s++)
#pragma unroll
            for (int nf = 0; nf < 8; nf++)
#pragma unroll
                for (int q = 0; q < 4; q++) acc[s][nf][q] = 0.f;

#pragma unroll
        for (int j = 0; j < 8; j++) {
            // ---- layer 1 chunk j: h[rows][16j..16j+15] (near-exact) ----
            uint32_t wh[2], wl[2];
            {
                const uint32_t a = (uint32_t)((j * 16 + (lane & 15)) * 16);
                ldmx2(wh[0], wh[1], w1h_base + a);
                ldmx2(wl[0], wl[1], w1l_base + a);
            }
            uint32_t Ah[2][4], Al[2][4];
#pragma unroll
            for (int s = 0; s < 2; s++) {
                const uint32_t A2[4] = { xh[s][0], xh[s][1], xl[s][0], xl[s][1] };
                float d[2][4];
#pragma unroll
                for (int nf = 0; nf < 2; nf++) {
                    d[nf][0] = d[nf][1] = d[nf][2] = d[nf][3] = 0.f;
                    const uint32_t B2[2] = { wh[nf], wh[nf] };
                    mma16(d[nf], A2, B2);       // xh*wh + xl*wh in one HMMA
                    mma8(d[nf], xh[s], wl[nf]); // + xh*wl
#pragma unroll
                    for (int q = 0; q < 4; q++) d[nf][q] = fmaxf(d[nf][q], 0.f);
                }
                // D(layer1) -> A(layer2) fragment identity, fp16 hi/lo split
                Ah[s][0] = cvt2(d[0][1], d[0][0]);
                Al[s][0] = cvt2(d[0][1] - hi_f(Ah[s][0]), d[0][0] - lo_f(Ah[s][0]));
                Ah[s][1] = cvt2(d[0][3], d[0][2]);
                Al[s][1] = cvt2(d[0][3] - hi_f(Ah[s][1]), d[0][2] - lo_f(Ah[s][1]));
                Ah[s][2] = cvt2(d[1][1], d[1][0]);
                Al[s][2] = cvt2(d[1][1] - hi_f(Ah[s][2]), d[1][0] - lo_f(Ah[s][2]));
                Ah[s][3] = cvt2(d[1][3], d[1][2]);
                Al[s][3] = cvt2(d[1][3] - hi_f(Ah[s][3]), d[1][2] - lo_f(Ah[s][3]));
            }

            // ---- layer 2: 2-term fp16 (Ah+Al) x Bh; B loads hoisted/half ----
#pragma unroll
            for (int half = 0; half < 2; half++) {
                uint32_t bh[2][2][2];   // [pp][frag][reg]
#pragma unroll
                for (int pp = 0; pp < 2; pp++) {
                    const uint32_t n = nrow + (uint32_t)((half * 2 + pp) * 16);
                    const uint32_t a = (n << 8) + ((((uint32_t)(2 * j) + klane) ^ (n & 7)) << 4);
                    ldmx4(bh[pp][0][0], bh[pp][0][1], bh[pp][1][0], bh[pp][1][1], w2h_base + a);
                }
                // 2 term-rounds of 8 independent MMAs
#pragma unroll
                for (int term = 0; term < 2; term++) {
#pragma unroll
                    for (int pp = 0; pp < 2; pp++)
#pragma unroll
                        for (int f = 0; f < 2; f++)
#pragma unroll
                            for (int s = 0; s < 2; s++) {
                                const int ai = (half * 2 + pp) * 2 + f;
                                const uint32_t* A = (term == 1) ? Al[s] : Ah[s];
                                mma16(acc[s][ai], A, bh[pp][f]);
                            }
                }
            }
        }

        // ---- epilogue: bias+relu, layer-3 dots, quad reduction, QP ----
        float P[4][4];
#pragma unroll
        for (int s = 0; s < 2; s++)
#pragma unroll
            for (int o = 0; o < 2; o++) {
                float pax = 0.f, pay = 0.f, pbx = 0.f, pby = 0.f;
#pragma unroll
                for (int nf = 0; nf < 8; nf++) {
                    const int n0 = nf * 8 + tig * 2;
                    const float4 e0 = s_ep[n0];
                    const float4 e1 = s_ep[n0 + 1];
                    const float y0 = fmaxf(acc[s][nf][o * 2 + 0] + e0.x, 0.f);
                    const float y1 = fmaxf(acc[s][nf][o * 2 + 1] + e1.x, 0.f);
                    if (nf < 4) {
                        pax = fmaf(y0, e0.y, fmaf(y1, e1.y, pax));
                        pay = fmaf(y0, e0.z, fmaf(y1, e1.z, pay));
                    } else {
                        pbx = fmaf(y0, e0.y, fmaf(y1, e1.y, pbx));
                        pby = fmaf(y0, e0.z, fmaf(y1, e1.z, pby));
                    }
                }
                P[s * 2 + o][0] = pax; P[s * 2 + o][1] = pay;
                P[s * 2 + o][2] = pbx; P[s * 2 + o][3] = pby;
            }
#pragma unroll
        for (int sl = 0; sl < 4; sl++)
#pragma unroll
            for (int c = 0; c < 4; c++) {
                P[sl][c] += __shfl_xor_sync(0xFFFFFFFFu, P[sl][c], 1);
                P[sl][c] += __shfl_xor_sync(0xFFFFFFFFu, P[sl][c], 2);
            }

        float uax, uay, ubx, uby;
        if      (tig == 0) { uax = P[0][0]; uay = P[0][1]; ubx = P[0][2]; uby = P[0][3]; }
        else if (tig == 1) { uax = P[1][0]; uay = P[1][1]; ubx = P[1][2]; uby = P[1][3]; }
        else if (tig == 2) { uax = P[2][0]; uay = P[2][1]; ubx = P[2][2]; uby = P[2][3]; }
        else               { uax = P[3][0]; uay = P[3][1]; ubx = P[3][2]; uby = P[3][3]; }

        const int gr = tbase + rl;
        if (gr < B) {
            const float px = s_x[rl][0] * s_ms[4] + s_ms[0];
            const float py = s_x[rl][1] * s_ms[5] + s_ms[1];
            const float th = s_x[rl][2] * s_ms[6] + s_ms[2];
            const float v  = s_x[rl][3] * s_ms[7] + s_ms[3];
            float s, c;
            sincosf(th, &s, &c);
            const float dx = px - 40.0f, dy = py - 15.0f;
            const float barrier = dx * dx + dy * dy - 36.0f;
            const float bdot = 2.0f * dx * v * c + 2.0f * dy * v * s;
            const float Lf2b = 2.0f * v * v;
            const float g1 = -(-2.0f * dx * v * s + 2.0f * dy * v * c);
            const float g2 = -(2.0f * dx * c + 2.0f * dy * s);

            const float u0x = -(uax + s_b3[0]);
            const float u0y = -(uay + s_b3[1]);
            const float z1 = ubx + s_b3[2];
            const float z2 = uby + s_b3[3];
            const float x32_0 = 4.0f / (1.0f + expf(-z1));
            const float x32_1 = 4.0f / (1.0f + expf(-z2));

            const float hq   = Lf2b + (x32_0 + x32_1) * bdot + x32_0 * x32_1 * barrier;
            const float viol = g1 * u0x + g2 * u0y - hq;
            const float gg   = g1 * g1 + g2 * g2;
            const float lam  = fmaxf(viol, 0.f) / (gg + 1e-12f);

            out[gr] = make_float2(u0x - lam * g1, u0y - lam * g2);
        }
    }
}

extern "C" void kernel_launch(void* const* d_in, const int* in_sizes, int n_in,
                              void* d_out, int out_size) {
    const float* x     = (const float*)d_in[0];
    const float* mean_ = (const float*)d_in[2];
    const float* std_  = (const float*)d_in[3];
    const float* w1    = (const float*)d_in[4];
    const float* b1    = (const float*)d_in[5];
    const float* w21   = (const float*)d_in[6];
    const float* b21   = (const float*)d_in[7];
    const float* w22   = (const float*)d_in[8];
    const float* b22   = (const float*)d_in[9];
    const float* w31   = (const float*)d_in[10];
    const float* b31   = (const float*)d_in[11];
    const float* w32   = (const float*)d_in[12];
    const float* b32   = (const float*)d_in[13];

    const int B = in_sizes[0] / 5;
    const int numTiles = (B + TILE_M - 1) / TILE_M;
    const int blocks = 296;   // 2 CTAs/SM x 148 SMs, persistent over tiles
    barriernet_mma_kernel<<<blocks, 256>>>(x, mean_, std_, w1, b1, w21, b21,
                                           w22, b22, w31, b31, w32, b32,
                                           (float2*)d_out, B, numTiles);
}